// round 11
// baseline (speedup 1.0000x reference)
#include <cuda_runtime.h>
#include <math.h>
#include <math_constants.h>

#define T_LEN   8192
#define N_SC    16
#define TTILE   512
#define NTH     256
#define HALO    258
#define SXN     1040                      // x tile + halo + slack (even, 16B-mult pairs)
#define SW      520                       // smem row stride for [18][SW] planes
#define MAXW    3408                      // >= sum of padded wavelet lengths (3368)
#define C1COLS  514                       // conv1 output cols (c = 1..514)

// ---------------- wavelet tables (filled by init kernel each launch) ----------------
__device__ float2 g_wtab[MAXW];           // padded: sh leading zeros, tail zeros to %4
__device__ int    g_Lp[N_SC];             // padded length (multiple of 4)
__device__ int    g_off[N_SC];            // padded offset (multiple of 4)
__device__ int    g_p[N_SC];              // half width L/2
__device__ int    g_sh[N_SC];             // leading zero taps
__device__ int    g_tot;

// LPT-balanced schedule: warp-pair grp handles these 4 scales (chunk = warp parity)
__constant__ int c_sched[4][4] = { {13,10,5,1}, {14,9,6,4}, {15,8,7,3}, {12,11,2,0} };

// Parallel init: grid (5 chunks, 16 scales) x 128 threads; ~1 tap/thread.
__global__ void wav_init_kernel()
{
    __shared__ double sh_sc[N_SC];
    __shared__ int    sh_L[N_SC];

    const double la = log10(2.0);
    const double lb = log10(200.0);
    const int tid = threadIdx.x;

    if (tid < N_SC) {
        double e = (tid == N_SC - 1) ? lb
                 : la + (lb - la) * ((double)tid / (double)(N_SC - 1));
        double sv = pow(10.0, e);
        int L = (int)(6.0 * sv);          // trunc, matches Python int()
        if (L > 512) L = 512;
        if ((L & 1) == 0) ++L;
        sh_sc[tid] = sv;
        sh_L[tid]  = L;
    }
    __syncthreads();

    const int s = blockIdx.y;             // this block's scale
    int off = 0, Lcur = 0, Shc = 0, Lpc = 0, tot = 0;
    #pragma unroll
    for (int i = 0; i < N_SC; ++i) {
        int L  = sh_L[i];
        int p  = L >> 1;
        int sh = ((2 - p) % 4 + 4) % 4;
        int lp = (L + sh + 3) & ~3;
        if (i < s) off += lp;
        if (i == s) { Lcur = L; Shc = sh; Lpc = lp; }
        tot += lp;
    }

    if (blockIdx.x == 0 && blockIdx.y == 0) {
        if (tid < N_SC) {
            int o2 = 0;
            int L = sh_L[tid], p = L >> 1;
            int sh = ((2 - p) % 4 + 4) % 4;
            int lp = (L + sh + 3) & ~3;
            for (int i = 0; i < tid; ++i) {
                int Li = sh_L[i], pi = Li >> 1;
                int shi = ((2 - pi) % 4 + 4) % 4;
                o2 += (Li + shi + 3) & ~3;
            }
            g_Lp[tid] = lp; g_off[tid] = o2; g_p[tid] = p; g_sh[tid] = sh;
        }
        if (tid == 0) g_tot = tot;
    }

    const int k = blockIdx.x * 128 + tid;
    if (k >= Lpc) return;
    const double sc = sh_sc[s];
    const int L = Lcur;
    float2 v = make_float2(0.f, 0.f);
    int ku = k - Shc;                     // unpadded tap index
    if (ku >= 0 && ku < L) {
        double lo = -(double)((L + 1) / 2);
        double hi =  (double)(L / 2);
        double t  = (ku == L - 1) ? hi : lo + (double)ku * ((double)L / (double)(L - 1));
        double ts = t / sc;
        double nrm = 1.0 / (pow(CUDART_PI, 0.25) * sqrt(sc));
        double g = nrm * exp(-0.5 * ts * ts);
        v = make_float2((float)(g * cos(5.0 * ts)), (float)(g * sin(5.0 * ts)));
    }
    g_wtab[off + k] = v;
}

// ---------------- packed f32x2 helpers ----------------
__device__ __forceinline__ void unpack2(unsigned long long a, float& lo, float& hi)
{
    unsigned ul, uh;
    asm("mov.b64 {%0, %1}, %2;" : "=r"(ul), "=r"(uh) : "l"(a));
    lo = __uint_as_float(ul); hi = __uint_as_float(uh);
}
#define FMA2(acc, w, xx) asm("fma.rn.f32x2 %0, %1, %2, %0;" : "+l"(acc) : "l"(w), "l"(xx))

// ---------------- fused CWT + correction-net + inverse kernel ----------------
__global__ __launch_bounds__(NTH, 2)
void wav_main_kernel(const float* __restrict__ x,
                     const float* __restrict__ w1,
                     const float* __restrict__ b1,
                     const float* __restrict__ w2,
                     const float* __restrict__ b2,
                     const float* __restrict__ blendl,
                     const float* __restrict__ lsc,
                     float* __restrict__ out)
{
    extern __shared__ float sm[];
    float*  sdx = sm;                       // 2*SXN: x tile stored as (v,v) pairs
    float2* swt = (float2*)(sm + 2 * SXN);  // MAXW float2 padded wavelets
    float*  scw = sm + 2 * SXN + 2 * MAXW;  // [18][SW] CWT magnitudes, rows 0/17 zero
    float*  sh1 = scw + 18 * SW;            // [18][SW] conv1+gelu, rows 0/17 zero
    float*  w1e = sh1 + 18 * SW;            // 144 folded conv1 weights
    float*  w2s = w1e + 144;                // 12 (9 used)
    int*    sLp = (int*)(w2s + 12);         // 16
    int*    sOf = sLp + 16;                 // 16
    int*    sP  = sOf + 16;                 // 16
    int*    sSh = sP + 16;                  // 16

    const int tid  = threadIdx.x;
    const int wid  = tid >> 5;
    const int lane = tid & 31;
    const int row  = blockIdx.y;            // b*C + c
    const int ch   = row & 31;
    const int t0   = blockIdx.x * TTILE;
    const float* xr = x + (size_t)row * T_LEN;

    // ---- phase A: loads (x stored pre-duplicated: sdx[2i]=sdx[2i+1]=x~[i]) ----
    for (int i = tid; i < SXN; i += NTH) {
        int g = t0 - HALO + i;
        if (g < 0) g = -g;                          // reflect
        if (g >= T_LEN) g = 2 * (T_LEN - 1) - g;
        float v = xr[g];
        ((float2*)sdx)[i] = make_float2(v, v);
    }
    const int tot = g_tot;
    for (int i = tid; i < tot; i += NTH) swt[i] = g_wtab[i];
    for (int i = tid; i < SW; i += NTH) {
        scw[i] = 0.f; scw[17 * SW + i] = 0.f;
        sh1[i] = 0.f; sh1[17 * SW + i] = 0.f;
    }
    if (tid < N_SC) {
        sLp[tid] = g_Lp[tid]; sOf[tid] = g_off[tid];
        sP[tid]  = g_p[tid];  sSh[tid] = g_sh[tid];
    }
    if (tid < 144) {
        int s = tid / 9, r = tid - s * 9, ds = r / 3;
        int si = s + ds - 1; si = si < 0 ? 0 : (si > 15 ? 15 : si);
        w1e[tid] = w1[ch * 9 + r] * expf(lsc[si]);
    }
    if (tid < 9) w2s[tid] = w2[ch * 9 + tid];
    __syncthreads();

    // ---- phase B1: main CWT, cols 2..513, 8 cols/lane, dup'd-x LDS, packed f32x2 ----
    const int grp = wid >> 1;                       // warp-pair id 0..3
    const int chk = wid & 1;                        // 256-col chunk 0/1
    #pragma unroll 1
    for (int it = 0; it < 4; ++it) {
        int s = c_sched[grp][it];
        int Lp = sLp[s];
        const ulonglong2* wp = (const ulonglong2*)swt + (sOf[s] >> 1);
        int c0 = 2 + (chk << 8) + (lane << 3);      // 8 consecutive cols per lane
        int st = c0 + 256 - sP[s] - sSh[s];         // multiple of 4 by construction
        const ulonglong2* dp = (const ulonglong2*)sdx + (st >> 1);  // 2 dup'd vals each

        ulonglong2 X0 = dp[0], X1 = dp[1], X2 = dp[2], X3 = dp[3];
        dp += 4;
        unsigned long long q0 = X0.x, q1 = X0.y, q2 = X1.x, q3 = X1.y,
                           q4 = X2.x, q5 = X2.y, q6 = X3.x, q7 = X3.y;
        unsigned long long a0 = 0ull, a1 = 0ull, a2 = 0ull, a3 = 0ull,
                           a4 = 0ull, a5 = 0ull, a6 = 0ull, a7 = 0ull;
        int nb = Lp >> 2;
        // weight double-buffer: block b's weights are loaded during block b-1
        ulonglong2 wA = wp[0], wB = wp[1];
        wp += 2;
        #pragma unroll 4
        for (int b = 0; b < nb; ++b) {
            ulonglong2 XA = dp[0], XB = dp[1];      // 4 new dup'd x values, no movs
            dp += 2;
            ulonglong2 nA = wp[0], nB = wp[1];      // weight prefetch, distance 1
            wp += 2;
            unsigned long long q8 = XA.x, q9 = XA.y, q10 = XB.x, q11 = XB.y;
            // tap 0: cols j use q[j]
            FMA2(a0, wA.x, q0); FMA2(a1, wA.x, q1); FMA2(a2, wA.x, q2); FMA2(a3, wA.x, q3);
            FMA2(a4, wA.x, q4); FMA2(a5, wA.x, q5); FMA2(a6, wA.x, q6); FMA2(a7, wA.x, q7);
            // tap 1
            FMA2(a0, wA.y, q1); FMA2(a1, wA.y, q2); FMA2(a2, wA.y, q3); FMA2(a3, wA.y, q4);
            FMA2(a4, wA.y, q5); FMA2(a5, wA.y, q6); FMA2(a6, wA.y, q7); FMA2(a7, wA.y, q8);
            // tap 2
            FMA2(a0, wB.x, q2); FMA2(a1, wB.x, q3); FMA2(a2, wB.x, q4); FMA2(a3, wB.x, q5);
            FMA2(a4, wB.x, q6); FMA2(a5, wB.x, q7); FMA2(a6, wB.x, q8); FMA2(a7, wB.x, q9);
            // tap 3
            FMA2(a0, wB.y, q3); FMA2(a1, wB.y, q4); FMA2(a2, wB.y, q5); FMA2(a3, wB.y, q6);
            FMA2(a4, wB.y, q7); FMA2(a5, wB.y, q8); FMA2(a6, wB.y, q9); FMA2(a7, wB.y, q10);
            // shift window by 4 (period-2 rename; unroll 4 keeps it mov-free)
            q0 = q4; q1 = q5; q2 = q6; q3 = q7;
            q4 = q8; q5 = q9; q6 = q10; q7 = q11;
            wA = nA; wB = nB;
        }
        float* dst = scw + (s + 1) * SW + c0;
        float cr, ci;
        unpack2(a0, cr, ci); dst[0] = sqrtf(fmaf(cr, cr, ci * ci));
        unpack2(a1, cr, ci); dst[1] = sqrtf(fmaf(cr, cr, ci * ci));
        unpack2(a2, cr, ci); dst[2] = sqrtf(fmaf(cr, cr, ci * ci));
        unpack2(a3, cr, ci); dst[3] = sqrtf(fmaf(cr, cr, ci * ci));
        unpack2(a4, cr, ci); dst[4] = sqrtf(fmaf(cr, cr, ci * ci));
        unpack2(a5, cr, ci); dst[5] = sqrtf(fmaf(cr, cr, ci * ci));
        unpack2(a6, cr, ci); dst[6] = sqrtf(fmaf(cr, cr, ci * ci));
        unpack2(a7, cr, ci); dst[7] = sqrtf(fmaf(cr, cr, ci * ci));
    }

    // ---- phase B2: halo cols {0,1,514,515}, tap-split + shuffle reduce ----
    {
        #pragma unroll 1
        for (int it = 0; it < 8; ++it) {
            int task = wid + (it << 3);             // 0..63
            int s = task >> 2, h = task & 3;
            int cc = (h == 0) ? 0 : (h == 1) ? 1 : (h == 2) ? 514 : 515;
            int Lp = sLp[s];
            int stc = cc + 256 - sP[s] - sSh[s];
            const float2* wp = swt + sOf[s];
            float re = 0.f, im = 0.f;
            for (int k = lane; k < Lp; k += 32) {
                int ix = stc + k; ix = ix < 0 ? 0 : ix;   // clamped: weight is 0 there
                float xv = sdx[2 * ix];
                float2 w = wp[k];
                re = fmaf(w.x, xv, re); im = fmaf(w.y, xv, im);
            }
            #pragma unroll
            for (int o = 16; o; o >>= 1) {
                re += __shfl_down_sync(0xffffffffu, re, o);
                im += __shfl_down_sync(0xffffffffu, im, o);
            }
            if (lane == 0) {
                int t = t0 - 2 + cc;
                scw[(s + 1) * SW + cc] =
                    ((unsigned)t < T_LEN) ? sqrtf(fmaf(re, re, im * im)) : 0.f;
            }
        }
    }
    __syncthreads();

    // ---- phase C: conv1 (scale-corr folded into weights) + exact GELU ----
    const float b1v = b1[ch];
    for (int item = tid; item < N_SC * C1COLS; item += NTH) {
        int s = item / C1COLS;
        int c = item - s * C1COLS + 1;              // 1..514
        int t = t0 - 2 + c;
        const float* r0 = scw + s * SW + (c - 1);
        const float* r1 = r0 + SW;
        const float* r2 = r1 + SW;
        const float* wv = w1e + s * 9;
        float v = b1v;
        v = fmaf(wv[0], r0[0], v); v = fmaf(wv[1], r0[1], v); v = fmaf(wv[2], r0[2], v);
        v = fmaf(wv[3], r1[0], v); v = fmaf(wv[4], r1[1], v); v = fmaf(wv[5], r1[2], v);
        v = fmaf(wv[6], r2[0], v); v = fmaf(wv[7], r2[1], v); v = fmaf(wv[8], r2[2], v);
        float g = 0.5f * v * (1.f + erff(v * 0.70710678118654752440f));
        // conv2's SAME zero-pad: h1 at t=-1 / t=8192 must be exactly 0
        sh1[(s + 1) * SW + c] = ((unsigned)t < T_LEN) ? g : 0.f;
    }
    __syncthreads();

    // ---- phase D: conv2 + GELU + blend + ratio-mean over scales + write ----
    const float blend = 1.f / (1.f + expf(-blendl[0]));
    const float b2v = b2[ch];
    float wl[9];
    #pragma unroll
    for (int i = 0; i < 9; ++i) wl[i] = w2s[i];
    for (int c = 2 + tid; c < TTILE + 2; c += NTH) {
        float acc = 0.f;
        #pragma unroll 4
        for (int s = 1; s <= N_SC; ++s) {
            const float* r0 = sh1 + (s - 1) * SW + (c - 1);
            const float* r1 = r0 + SW;
            const float* r2 = r1 + SW;
            float v = b2v;
            v = fmaf(wl[0], r0[0], v); v = fmaf(wl[1], r0[1], v); v = fmaf(wl[2], r0[2], v);
            v = fmaf(wl[3], r1[0], v); v = fmaf(wl[4], r1[1], v); v = fmaf(wl[5], r1[2], v);
            v = fmaf(wl[6], r2[0], v); v = fmaf(wl[7], r2[1], v); v = fmaf(wl[8], r2[2], v);
            float h  = 0.5f * v * (1.f + erff(v * 0.70710678118654752440f));
            float cw = scw[s * SW + c];
            float bl = blend * h + (1.f - blend) * cw;
            acc += __fdividef(bl, cw + 1e-8f);
        }
        out[(size_t)row * T_LEN + (t0 + c - 2)] = sdx[2 * (c + 256)] * acc * (1.f / 16.f);
    }
}

extern "C" void kernel_launch(void* const* d_in, const int* in_sizes, int n_in,
                              void* d_out, int out_size)
{
    const float* x  = (const float*)d_in[0];
    const float* w1 = (const float*)d_in[1];
    const float* b1 = (const float*)d_in[2];
    const float* w2 = (const float*)d_in[3];
    const float* b2 = (const float*)d_in[4];
    const float* bl = (const float*)d_in[5];
    const float* ls = (const float*)d_in[6];
    float* out = (float*)d_out;

    const int rows = in_sizes[0] / T_LEN;   // B*C = 256

    const size_t smem = (size_t)(2 * SXN + 2 * MAXW + 2 * 18 * SW + 144 + 12) * sizeof(float)
                        + 4 * 16 * sizeof(int);
    cudaFuncSetAttribute(wav_main_kernel, cudaFuncAttributeMaxDynamicSharedMemorySize, (int)smem);

    dim3 igrid(5, N_SC);                   // 5 tap-chunks x 16 scales
    wav_init_kernel<<<igrid, 128>>>();
    dim3 grid(T_LEN / TTILE, rows);
    wav_main_kernel<<<grid, NTH, smem>>>(x, w1, b1, w2, b2, bl, ls, out);
}

// round 12
// speedup vs baseline: 1.6886x; 1.6886x over previous
#include <cuda_runtime.h>
#include <math.h>
#include <math_constants.h>

#define T_LEN   8192
#define N_SC    16
#define TTILE   512
#define NTH     256
#define HALO    258
#define SXN     1040                      // x tile + halo + slack (16B-mult count)
#define SW      520                       // smem row stride for scw/ring planes
#define MAXW    3368                      // exact sum of padded wavelet lengths
#define C1COLS  514                       // conv1 output cols (c = 1..514)

// ---------------- wavelet tables (filled by init kernel each launch) ----------------
__device__ float2 g_wtab[MAXW];           // padded: sh leading zeros, tail zeros to %4
__device__ int    g_Lp[N_SC];             // padded length (multiple of 4)
__device__ int    g_off[N_SC];            // padded offset (multiple of 4)
__device__ int    g_p[N_SC];              // half width L/2
__device__ int    g_sh[N_SC];             // leading zero taps
__device__ int    g_tot;

// LPT-balanced schedule: warp-pair grp handles these 4 scales (chunk = warp parity)
__constant__ int c_sched[4][4] = { {13,10,5,1}, {14,9,6,4}, {15,8,7,3}, {12,11,2,0} };

// Parallel init: grid (5 chunks, 16 scales) x 128 threads; ~1 tap/thread.
__global__ void wav_init_kernel()
{
    __shared__ double sh_sc[N_SC];
    __shared__ int    sh_L[N_SC];

    const double la = log10(2.0);
    const double lb = log10(200.0);
    const int tid = threadIdx.x;

    if (tid < N_SC) {
        double e = (tid == N_SC - 1) ? lb
                 : la + (lb - la) * ((double)tid / (double)(N_SC - 1));
        double sv = pow(10.0, e);
        int L = (int)(6.0 * sv);          // trunc, matches Python int()
        if (L > 512) L = 512;
        if ((L & 1) == 0) ++L;
        sh_sc[tid] = sv;
        sh_L[tid]  = L;
    }
    __syncthreads();

    const int s = blockIdx.y;             // this block's scale
    int off = 0, Lcur = 0, Shc = 0, Lpc = 0, tot = 0;
    #pragma unroll
    for (int i = 0; i < N_SC; ++i) {
        int L  = sh_L[i];
        int p  = L >> 1;
        int sh = ((2 - p) % 4 + 4) % 4;
        int lp = (L + sh + 3) & ~3;
        if (i < s) off += lp;
        if (i == s) { Lcur = L; Shc = sh; Lpc = lp; }
        tot += lp;
    }

    if (blockIdx.x == 0 && blockIdx.y == 0) {
        if (tid < N_SC) {
            int o2 = 0;
            int L = sh_L[tid], p = L >> 1;
            int sh = ((2 - p) % 4 + 4) % 4;
            int lp = (L + sh + 3) & ~3;
            for (int i = 0; i < tid; ++i) {
                int Li = sh_L[i], pi = Li >> 1;
                int shi = ((2 - pi) % 4 + 4) % 4;
                o2 += (Li + shi + 3) & ~3;
            }
            g_Lp[tid] = lp; g_off[tid] = o2; g_p[tid] = p; g_sh[tid] = sh;
        }
        if (tid == 0) g_tot = tot;
    }

    const int k = blockIdx.x * 128 + tid;
    if (k >= Lpc) return;
    const double sc = sh_sc[s];
    const int L = Lcur;
    float2 v = make_float2(0.f, 0.f);
    int ku = k - Shc;                     // unpadded tap index
    if (ku >= 0 && ku < L) {
        double lo = -(double)((L + 1) / 2);
        double hi =  (double)(L / 2);
        double t  = (ku == L - 1) ? hi : lo + (double)ku * ((double)L / (double)(L - 1));
        double ts = t / sc;
        double nrm = 1.0 / (pow(CUDART_PI, 0.25) * sqrt(sc));
        double g = nrm * exp(-0.5 * ts * ts);
        v = make_float2((float)(g * cos(5.0 * ts)), (float)(g * sin(5.0 * ts)));
    }
    g_wtab[off + k] = v;
}

// ---------------- packed f32x2 helpers ----------------
__device__ __forceinline__ unsigned long long packdup(float v)
{
    unsigned long long r;
    unsigned u = __float_as_uint(v);
    asm("mov.b64 %0, {%1, %1};" : "=l"(r) : "r"(u));
    return r;
}
__device__ __forceinline__ void unpack2(unsigned long long a, float& lo, float& hi)
{
    unsigned ul, uh;
    asm("mov.b64 {%0, %1}, %2;" : "=r"(ul), "=r"(uh) : "l"(a));
    lo = __uint_as_float(ul); hi = __uint_as_float(uh);
}
#define FMA2(acc, w, xx) asm("fma.rn.f32x2 %0, %1, %2, %0;" : "+l"(acc) : "l"(w), "l"(xx))

__device__ __forceinline__ float gelu_exact(float v)
{
    return 0.5f * v * (1.f + erff(v * 0.70710678118654752440f));
}
__device__ __forceinline__ float conv_row(const float* r, const float* w, float v)
{
    v = fmaf(w[0], r[0], v); v = fmaf(w[1], r[1], v); return fmaf(w[2], r[2], v);
}

// ---------------- fused CWT + correction-net + inverse kernel ----------------
__global__ __launch_bounds__(NTH, 3)
void wav_main_kernel(const float* __restrict__ x,
                     const float* __restrict__ w1,
                     const float* __restrict__ b1,
                     const float* __restrict__ w2,
                     const float* __restrict__ b2,
                     const float* __restrict__ blendl,
                     const float* __restrict__ lsc,
                     float* __restrict__ out)
{
    extern __shared__ float sm[];
    float*  sx  = sm;                       // SXN: x tile + reflect halo (16B aligned)
    float2* swt = (float2*)(sm + SXN);      // MAXW float2 padded wavelets
    float*  scw = sm + SXN + 2 * MAXW;      // [18][SW] CWT magnitudes, rows 0/17 zero
    float*  shr = scw + 18 * SW;            // [4][SW] conv1+gelu RING (row r -> slot r&3)
    float*  w1e = shr + 4 * SW;             // 144 folded conv1 weights
    float*  w2s = w1e + 144;                // 12 (9 used)
    int*    sLp = (int*)(w2s + 12);         // 16
    int*    sOf = sLp + 16;                 // 16
    int*    sP  = sOf + 16;                 // 16
    int*    sSh = sP + 16;                  // 16

    const int tid  = threadIdx.x;
    const int wid  = tid >> 5;
    const int lane = tid & 31;
    const int row  = blockIdx.y;            // b*C + c
    const int ch   = row & 31;
    const int t0   = blockIdx.x * TTILE;
    const float* xr = x + (size_t)row * T_LEN;

    // ---- phase A: loads ----
    for (int i = tid; i < SXN; i += NTH) {
        int g = t0 - HALO + i;
        if (g < 0) g = -g;                          // reflect
        if (g >= T_LEN) g = 2 * (T_LEN - 1) - g;
        sx[i] = xr[g];
    }
    const int tot = g_tot;
    for (int i = tid; i < tot; i += NTH) swt[i] = g_wtab[i];
    for (int i = tid; i < SW; i += NTH) {           // scw pad rows only
        scw[i] = 0.f; scw[17 * SW + i] = 0.f;
    }
    if (tid < N_SC) {
        sLp[tid] = g_Lp[tid]; sOf[tid] = g_off[tid];
        sP[tid]  = g_p[tid];  sSh[tid] = g_sh[tid];
    }
    if (tid < 144) {
        int s = tid / 9, r = tid - s * 9, ds = r / 3;
        int si = s + ds - 1; si = si < 0 ? 0 : (si > 15 ? 15 : si);
        w1e[tid] = w1[ch * 9 + r] * expf(lsc[si]);
    }
    if (tid < 9) w2s[tid] = w2[ch * 9 + tid];
    __syncthreads();

    // ---- phase B1: main CWT, cols 2..513, 8 cols/lane, LPT units, packed f32x2 ----
    const int grp = wid >> 1;                       // warp-pair id 0..3
    const int chk = wid & 1;                        // 256-col chunk 0/1
    #pragma unroll 1
    for (int it = 0; it < 4; ++it) {
        int s = c_sched[grp][it];
        int Lp = sLp[s];
        const ulonglong2* wp = (const ulonglong2*)swt + (sOf[s] >> 1);
        int c0 = 2 + (chk << 8) + (lane << 3);      // 8 consecutive cols per lane
        int st = c0 + 256 - sP[s] - sSh[s];         // multiple of 4 by construction
        const float4* xv4 = (const float4*)(sx + st);
        float4 xa = xv4[0];
        float4 xb = xv4[1];
        unsigned long long q0 = packdup(xa.x), q1 = packdup(xa.y),
                           q2 = packdup(xa.z), q3 = packdup(xa.w);
        unsigned long long q4 = packdup(xb.x), q5 = packdup(xb.y),
                           q6 = packdup(xb.z), q7 = packdup(xb.w);
        unsigned long long a0 = 0ull, a1 = 0ull, a2 = 0ull, a3 = 0ull,
                           a4 = 0ull, a5 = 0ull, a6 = 0ull, a7 = 0ull;
        int nb = Lp >> 2;
        ulonglong2 wA = wp[0], wB = wp[1];
        wp += 2;
        #pragma unroll 4
        for (int b = 0; b < nb; ++b) {
            float4 xn = xv4[b + 2];                 // x prefetch, distance 2
            ulonglong2 nA = wp[0], nB = wp[1];      // weight prefetch, distance 1
            wp += 2;
            unsigned long long q8  = packdup(xn.x), q9  = packdup(xn.y),
                               q10 = packdup(xn.z), q11 = packdup(xn.w);
            FMA2(a0, wA.x, q0); FMA2(a1, wA.x, q1); FMA2(a2, wA.x, q2); FMA2(a3, wA.x, q3);
            FMA2(a4, wA.x, q4); FMA2(a5, wA.x, q5); FMA2(a6, wA.x, q6); FMA2(a7, wA.x, q7);
            FMA2(a0, wA.y, q1); FMA2(a1, wA.y, q2); FMA2(a2, wA.y, q3); FMA2(a3, wA.y, q4);
            FMA2(a4, wA.y, q5); FMA2(a5, wA.y, q6); FMA2(a6, wA.y, q7); FMA2(a7, wA.y, q8);
            FMA2(a0, wB.x, q2); FMA2(a1, wB.x, q3); FMA2(a2, wB.x, q4); FMA2(a3, wB.x, q5);
            FMA2(a4, wB.x, q6); FMA2(a5, wB.x, q7); FMA2(a6, wB.x, q8); FMA2(a7, wB.x, q9);
            FMA2(a0, wB.y, q3); FMA2(a1, wB.y, q4); FMA2(a2, wB.y, q5); FMA2(a3, wB.y, q6);
            FMA2(a4, wB.y, q7); FMA2(a5, wB.y, q8); FMA2(a6, wB.y, q9); FMA2(a7, wB.y, q10);
            q0 = q4; q1 = q5; q2 = q6; q3 = q7;
            q4 = q8; q5 = q9; q6 = q10; q7 = q11;
            wA = nA; wB = nB;
        }
        float* dst = scw + (s + 1) * SW + c0;
        float cr, ci;
        unpack2(a0, cr, ci); dst[0] = sqrtf(fmaf(cr, cr, ci * ci));
        unpack2(a1, cr, ci); dst[1] = sqrtf(fmaf(cr, cr, ci * ci));
        unpack2(a2, cr, ci); dst[2] = sqrtf(fmaf(cr, cr, ci * ci));
        unpack2(a3, cr, ci); dst[3] = sqrtf(fmaf(cr, cr, ci * ci));
        unpack2(a4, cr, ci); dst[4] = sqrtf(fmaf(cr, cr, ci * ci));
        unpack2(a5, cr, ci); dst[5] = sqrtf(fmaf(cr, cr, ci * ci));
        unpack2(a6, cr, ci); dst[6] = sqrtf(fmaf(cr, cr, ci * ci));
        unpack2(a7, cr, ci); dst[7] = sqrtf(fmaf(cr, cr, ci * ci));
    }

    // ---- phase B2: halo cols {0,1,514,515}, tap-split + shuffle reduce ----
    {
        #pragma unroll 1
        for (int it = 0; it < 8; ++it) {
            int task = wid + (it << 3);             // 0..63
            int s = task >> 2, h = task & 3;
            int cc = (h == 0) ? 0 : (h == 1) ? 1 : (h == 2) ? 514 : 515;
            int Lp = sLp[s];
            int stc = cc + 256 - sP[s] - sSh[s];
            const float2* wp = swt + sOf[s];
            float re = 0.f, im = 0.f;
            for (int k = lane; k < Lp; k += 32) {
                int ix = stc + k; ix = ix < 0 ? 0 : ix;   // clamped: weight is 0 there
                float xv = sx[ix];
                float2 w = wp[k];
                re = fmaf(w.x, xv, re); im = fmaf(w.y, xv, im);
            }
            #pragma unroll
            for (int o = 16; o; o >>= 1) {
                re += __shfl_down_sync(0xffffffffu, re, o);
                im += __shfl_down_sync(0xffffffffu, im, o);
            }
            if (lane == 0) {
                int t = t0 - 2 + cc;
                scw[(s + 1) * SW + cc] =
                    ((unsigned)t < T_LEN) ? sqrtf(fmaf(re, re, im * im)) : 0.f;
            }
        }
    }
    __syncthreads();

    // ---- phase CD: fused conv1+GELU (ring rows) and conv2+GELU+blend+ratio ----
    const float blend = 1.f / (1.f + expf(-blendl[0]));
    const float b1v = b1[ch];
    const float b2v = b2[ch];
    float wl[9];
    #pragma unroll
    for (int i = 0; i < 9; ++i) wl[i] = w2s[i];
    float acc0 = 0.f, acc1 = 0.f;
    const int cD0 = 2 + tid, cD1 = 258 + tid;       // each thread owns 2 output cols

    #pragma unroll 1
    for (int s = 1; s <= N_SC; ++s) {
        // conv1 row s (scale s-1) into ring slot s&3, cols 1..514
        {
            float* dstr = shr + (s & 3) * SW;
            const float* wv = w1e + (s - 1) * 9;
            #pragma unroll
            for (int j = 0; j < 3; ++j) {
                int c = 1 + tid + (j << 8);         // 1+tid, 257+tid, 513+tid
                if (j < 2 || tid < 2) {
                    const float* p0 = scw + (s - 1) * SW + (c - 1);
                    float v = b1v;
                    v = conv_row(p0,          wv,     v);
                    v = conv_row(p0 + SW,     wv + 3, v);
                    v = conv_row(p0 + 2 * SW, wv + 6, v);
                    int t = t0 - 2 + c;
                    dstr[c] = ((unsigned)t < T_LEN) ? gelu_exact(v) : 0.f;
                }
            }
        }
        __syncthreads();
        if (s >= 2) {
            // conv2 + blend + ratio for scale sc = s-1 (ring rows sc-1, sc, sc+1)
            int sc = s - 1;
            #pragma unroll
            for (int j = 0; j < 2; ++j) {
                int c = (j == 0) ? cD0 : cD1;
                float v = b2v;
                if (sc > 1)  v = conv_row(shr + ((sc - 1) & 3) * SW + (c - 1), wl,     v);
                v = conv_row(shr + (sc & 3) * SW + (c - 1), wl + 3, v);
                v = conv_row(shr + ((sc + 1) & 3) * SW + (c - 1), wl + 6, v);
                float h  = gelu_exact(v);
                float cw = scw[sc * SW + c];
                float bl = blend * h + (1.f - blend) * cw;
                float r  = __fdividef(bl, cw + 1e-8f);
                if (j == 0) acc0 += r; else acc1 += r;
            }
        }
    }
    // conv2 for scale 16 (ring rows 15, 16; row 17 is zero -> skipped)
    {
        int sc = N_SC;
        #pragma unroll
        for (int j = 0; j < 2; ++j) {
            int c = (j == 0) ? cD0 : cD1;
            float v = b2v;
            v = conv_row(shr + ((sc - 1) & 3) * SW + (c - 1), wl,     v);
            v = conv_row(shr + (sc & 3) * SW + (c - 1), wl + 3, v);
            float h  = gelu_exact(v);
            float cw = scw[sc * SW + c];
            float bl = blend * h + (1.f - blend) * cw;
            float r  = __fdividef(bl, cw + 1e-8f);
            if (j == 0) acc0 += r; else acc1 += r;
        }
    }
    out[(size_t)row * T_LEN + (t0 + cD0 - 2)] = sx[cD0 + 256] * acc0 * (1.f / 16.f);
    out[(size_t)row * T_LEN + (t0 + cD1 - 2)] = sx[cD1 + 256] * acc1 * (1.f / 16.f);
}

extern "C" void kernel_launch(void* const* d_in, const int* in_sizes, int n_in,
                              void* d_out, int out_size)
{
    const float* x  = (const float*)d_in[0];
    const float* w1 = (const float*)d_in[1];
    const float* b1 = (const float*)d_in[2];
    const float* w2 = (const float*)d_in[3];
    const float* b2 = (const float*)d_in[4];
    const float* bl = (const float*)d_in[5];
    const float* ls = (const float*)d_in[6];
    float* out = (float*)d_out;

    const int rows = in_sizes[0] / T_LEN;   // B*C = 256

    const size_t smem = (size_t)(SXN + 2 * MAXW + 18 * SW + 4 * SW + 144 + 12) * sizeof(float)
                        + 4 * 16 * sizeof(int);      // = 77,744 B -> 3 CTAs/SM
    cudaFuncSetAttribute(wav_main_kernel, cudaFuncAttributeMaxDynamicSharedMemorySize, (int)smem);

    dim3 igrid(5, N_SC);                   // 5 tap-chunks x 16 scales
    wav_init_kernel<<<igrid, 128>>>();
    dim3 grid(T_LEN / TTILE, rows);
    wav_main_kernel<<<grid, NTH, smem>>>(x, w1, b1, w2, b2, bl, ls, out);
}

// round 15
// speedup vs baseline: 1.7737x; 1.0504x over previous
#include <cuda_runtime.h>
#include <math.h>
#include <math_constants.h>

#define T_LEN   8192
#define N_SC    16
#define TTILE   512
#define NTH     256
#define HALO    258
#define SXN     1040                      // x tile + halo + slack (16B-mult count)
#define SW      520                       // smem row stride for scw/ring planes
#define MAXW    3368                      // exact sum of padded wavelet lengths
#define C1COLS  514                       // conv1 output cols (c = 1..514)

// ---------------- wavelet tables (filled by init kernel each launch) ----------------
__device__ float2 g_wtab[MAXW];           // padded: sh leading zeros, tail zeros to %4
__device__ int    g_Lp[N_SC];             // padded length (multiple of 4)
__device__ int    g_off[N_SC];            // padded offset (multiple of 4)
__device__ int    g_p[N_SC];              // half width L/2
__device__ int    g_sh[N_SC];             // leading zero taps
__device__ int    g_tot;

// LPT-balanced schedule: warp-pair grp handles these 4 scales (chunk = warp parity)
__constant__ int c_sched[4][4] = { {13,10,5,1}, {14,9,6,4}, {15,8,7,3}, {12,11,2,0} };

// Parallel init: grid (5 chunks, 16 scales) x 128 threads; ~1 tap/thread.
__global__ void wav_init_kernel()
{
    __shared__ double sh_sc[N_SC];
    __shared__ int    sh_L[N_SC];

    const double la = log10(2.0);
    const double lb = log10(200.0);
    const int tid = threadIdx.x;

    if (tid < N_SC) {
        double e = (tid == N_SC - 1) ? lb
                 : la + (lb - la) * ((double)tid / (double)(N_SC - 1));
        double sv = pow(10.0, e);
        int L = (int)(6.0 * sv);          // trunc, matches Python int()
        if (L > 512) L = 512;
        if ((L & 1) == 0) ++L;
        sh_sc[tid] = sv;
        sh_L[tid]  = L;
    }
    __syncthreads();

    const int s = blockIdx.y;             // this block's scale
    int off = 0, Lcur = 0, Shc = 0, Lpc = 0, tot = 0;
    #pragma unroll
    for (int i = 0; i < N_SC; ++i) {
        int L  = sh_L[i];
        int p  = L >> 1;
        int sh = ((2 - p) % 4 + 4) % 4;
        int lp = (L + sh + 3) & ~3;
        if (i < s) off += lp;
        if (i == s) { Lcur = L; Shc = sh; Lpc = lp; }
        tot += lp;
    }

    if (blockIdx.x == 0 && blockIdx.y == 0) {
        if (tid < N_SC) {
            int o2 = 0;
            int L = sh_L[tid], p = L >> 1;
            int sh = ((2 - p) % 4 + 4) % 4;
            int lp = (L + sh + 3) & ~3;
            for (int i = 0; i < tid; ++i) {
                int Li = sh_L[i], pi = Li >> 1;
                int shi = ((2 - pi) % 4 + 4) % 4;
                o2 += (Li + shi + 3) & ~3;
            }
            g_Lp[tid] = lp; g_off[tid] = o2; g_p[tid] = p; g_sh[tid] = sh;
        }
        if (tid == 0) g_tot = tot;
    }

    const int k = blockIdx.x * 128 + tid;
    if (k >= Lpc) return;
    const double sc = sh_sc[s];
    const int L = Lcur;
    float2 v = make_float2(0.f, 0.f);
    int ku = k - Shc;                     // unpadded tap index
    if (ku >= 0 && ku < L) {
        double lo = -(double)((L + 1) / 2);
        double hi =  (double)(L / 2);
        double t  = (ku == L - 1) ? hi : lo + (double)ku * ((double)L / (double)(L - 1));
        double ts = t / sc;
        double nrm = 1.0 / (pow(CUDART_PI, 0.25) * sqrt(sc));
        double g = nrm * exp(-0.5 * ts * ts);
        v = make_float2((float)(g * cos(5.0 * ts)), (float)(g * sin(5.0 * ts)));
    }
    g_wtab[off + k] = v;
}

// ---------------- packed f32x2 helpers ----------------
__device__ __forceinline__ unsigned long long packdup(float v)
{
    unsigned long long r;
    unsigned u = __float_as_uint(v);
    asm("mov.b64 %0, {%1, %1};" : "=l"(r) : "r"(u));
    return r;
}
__device__ __forceinline__ void unpack2(unsigned long long a, float& lo, float& hi)
{
    unsigned ul, uh;
    asm("mov.b64 {%0, %1}, %2;" : "=r"(ul), "=r"(uh) : "l"(a));
    lo = __uint_as_float(ul); hi = __uint_as_float(uh);
}
#define FMA2(acc, w, xx) asm("fma.rn.f32x2 %0, %1, %2, %0;" : "+l"(acc) : "l"(w), "l"(xx))

__device__ __forceinline__ float gelu_exact(float v)
{
    return 0.5f * v * (1.f + erff(v * 0.70710678118654752440f));
}
__device__ __forceinline__ float conv_row(const float* r, const float* w, float v)
{
    v = fmaf(w[0], r[0], v); v = fmaf(w[1], r[1], v); return fmaf(w[2], r[2], v);
}

// ---------------- fused CWT + correction-net + inverse kernel ----------------
__global__ __launch_bounds__(NTH, 3)
void wav_main_kernel(const float* __restrict__ x,
                     const float* __restrict__ w1,
                     const float* __restrict__ b1,
                     const float* __restrict__ w2,
                     const float* __restrict__ b2,
                     const float* __restrict__ blendl,
                     const float* __restrict__ lsc,
                     float* __restrict__ out)
{
    extern __shared__ float sm[];
    float*  sx  = sm;                       // SXN: x tile + reflect halo (16B aligned)
    float2* swt = (float2*)(sm + SXN);      // MAXW float2 padded wavelets
    float*  scw = sm + SXN + 2 * MAXW;      // [16][SW] CWT magnitudes (scale s -> row s)
    float*  shr = scw + 16 * SW;            // [4][SW] conv1+gelu RING (row r -> slot r&3)
    float*  w1e = shr + 4 * SW;             // 144 folded conv1 weights
    float*  w2s = w1e + 144;                // 12 (9 used)
    int*    sLp = (int*)(w2s + 12);         // 16
    int*    sOf = sLp + 16;                 // 16
    int*    sP  = sOf + 16;                 // 16
    int*    sSh = sP + 16;                  // 16

    const int tid  = threadIdx.x;
    const int wid  = tid >> 5;
    const int lane = tid & 31;
    const int row  = blockIdx.y;            // b*C + c
    const int ch   = row & 31;
    const int t0   = blockIdx.x * TTILE;
    const float* xr = x + (size_t)row * T_LEN;

    // ---- phase A: loads ----
    for (int i = tid; i < SXN; i += NTH) {
        int g = t0 - HALO + i;
        if (g < 0) g = -g;                          // reflect
        if (g >= T_LEN) g = 2 * (T_LEN - 1) - g;
        sx[i] = xr[g];
    }
    const int tot = g_tot;
    for (int i = tid; i < tot; i += NTH) swt[i] = g_wtab[i];
    if (tid < N_SC) {
        sLp[tid] = g_Lp[tid]; sOf[tid] = g_off[tid];
        sP[tid]  = g_p[tid];  sSh[tid] = g_sh[tid];
    }
    if (tid < 144) {
        int s = tid / 9, r = tid - s * 9, ds = r / 3;
        int si = s + ds - 1; si = si < 0 ? 0 : (si > 15 ? 15 : si);
        w1e[tid] = w1[ch * 9 + r] * expf(lsc[si]);
    }
    if (tid < 9) w2s[tid] = w2[ch * 9 + tid];
    __syncthreads();

    // ---- phase B1: main CWT, cols 2..513, 8 cols/lane, LPT units, packed f32x2 ----
    const int grp = wid >> 1;                       // warp-pair id 0..3
    const int chk = wid & 1;                        // 256-col chunk 0/1
    #pragma unroll 1
    for (int it = 0; it < 4; ++it) {
        int s = c_sched[grp][it];
        int Lp = sLp[s];
        const ulonglong2* wp = (const ulonglong2*)swt + (sOf[s] >> 1);
        int c0 = 2 + (chk << 8) + (lane << 3);      // 8 consecutive cols per lane
        int st = c0 + 256 - sP[s] - sSh[s];         // multiple of 4 by construction
        const float4* xv4 = (const float4*)(sx + st);
        float4 xa = xv4[0];
        float4 xb = xv4[1];
        unsigned long long q0 = packdup(xa.x), q1 = packdup(xa.y),
                           q2 = packdup(xa.z), q3 = packdup(xa.w);
        unsigned long long q4 = packdup(xb.x), q5 = packdup(xb.y),
                           q6 = packdup(xb.z), q7 = packdup(xb.w);
        unsigned long long a0 = 0ull, a1 = 0ull, a2 = 0ull, a3 = 0ull,
                           a4 = 0ull, a5 = 0ull, a6 = 0ull, a7 = 0ull;
        int nb = Lp >> 2;
        ulonglong2 wA = wp[0], wB = wp[1];
        wp += 2;
        #pragma unroll 4
        for (int b = 0; b < nb; ++b) {
            float4 xn = xv4[b + 2];                 // x prefetch, distance 2
            ulonglong2 nA = wp[0], nB = wp[1];      // weight prefetch, distance 1
            wp += 2;
            unsigned long long q8  = packdup(xn.x), q9  = packdup(xn.y),
                               q10 = packdup(xn.z), q11 = packdup(xn.w);
            FMA2(a0, wA.x, q0); FMA2(a1, wA.x, q1); FMA2(a2, wA.x, q2); FMA2(a3, wA.x, q3);
            FMA2(a4, wA.x, q4); FMA2(a5, wA.x, q5); FMA2(a6, wA.x, q6); FMA2(a7, wA.x, q7);
            FMA2(a0, wA.y, q1); FMA2(a1, wA.y, q2); FMA2(a2, wA.y, q3); FMA2(a3, wA.y, q4);
            FMA2(a4, wA.y, q5); FMA2(a5, wA.y, q6); FMA2(a6, wA.y, q7); FMA2(a7, wA.y, q8);
            FMA2(a0, wB.x, q2); FMA2(a1, wB.x, q3); FMA2(a2, wB.x, q4); FMA2(a3, wB.x, q5);
            FMA2(a4, wB.x, q6); FMA2(a5, wB.x, q7); FMA2(a6, wB.x, q8); FMA2(a7, wB.x, q9);
            FMA2(a0, wB.y, q3); FMA2(a1, wB.y, q4); FMA2(a2, wB.y, q5); FMA2(a3, wB.y, q6);
            FMA2(a4, wB.y, q7); FMA2(a5, wB.y, q8); FMA2(a6, wB.y, q9); FMA2(a7, wB.y, q10);
            q0 = q4; q1 = q5; q2 = q6; q3 = q7;
            q4 = q8; q5 = q9; q6 = q10; q7 = q11;
            wA = nA; wB = nB;
        }
        float* dst = scw + s * SW + c0;
        float cr, ci;
        unpack2(a0, cr, ci); dst[0] = sqrtf(fmaf(cr, cr, ci * ci));
        unpack2(a1, cr, ci); dst[1] = sqrtf(fmaf(cr, cr, ci * ci));
        unpack2(a2, cr, ci); dst[2] = sqrtf(fmaf(cr, cr, ci * ci));
        unpack2(a3, cr, ci); dst[3] = sqrtf(fmaf(cr, cr, ci * ci));
        unpack2(a4, cr, ci); dst[4] = sqrtf(fmaf(cr, cr, ci * ci));
        unpack2(a5, cr, ci); dst[5] = sqrtf(fmaf(cr, cr, ci * ci));
        unpack2(a6, cr, ci); dst[6] = sqrtf(fmaf(cr, cr, ci * ci));
        unpack2(a7, cr, ci); dst[7] = sqrtf(fmaf(cr, cr, ci * ci));
    }

    // ---- phase B2: halo cols {0,1,514,515}, tap-split + shuffle reduce ----
    {
        #pragma unroll 1
        for (int it = 0; it < 8; ++it) {
            int task = wid + (it << 3);             // 0..63
            int s = task >> 2, h = task & 3;
            int cc = (h == 0) ? 0 : (h == 1) ? 1 : (h == 2) ? 514 : 515;
            int Lp = sLp[s];
            int stc = cc + 256 - sP[s] - sSh[s];
            const float2* wp = swt + sOf[s];
            float re = 0.f, im = 0.f;
            for (int k = lane; k < Lp; k += 32) {
                int ix = stc + k; ix = ix < 0 ? 0 : ix;   // clamped: weight is 0 there
                float xv = sx[ix];
                float2 w = wp[k];
                re = fmaf(w.x, xv, re); im = fmaf(w.y, xv, im);
            }
            #pragma unroll
            for (int o = 16; o; o >>= 1) {
                re += __shfl_down_sync(0xffffffffu, re, o);
                im += __shfl_down_sync(0xffffffffu, im, o);
            }
            if (lane == 0) {
                int t = t0 - 2 + cc;
                scw[s * SW + cc] =
                    ((unsigned)t < T_LEN) ? sqrtf(fmaf(re, re, im * im)) : 0.f;
            }
        }
    }
    __syncthreads();

    // ---- phase CD: fused conv1+GELU (ring rows) and conv2+GELU+blend+ratio ----
    const float blend = 1.f / (1.f + expf(-blendl[0]));
    const float b1v = b1[ch];
    const float b2v = b2[ch];
    float wl[9];
    #pragma unroll
    for (int i = 0; i < 9; ++i) wl[i] = w2s[i];
    float acc0 = 0.f, acc1 = 0.f;
    const int cD0 = 2 + tid, cD1 = 258 + tid;       // each thread owns 2 output cols

    #pragma unroll 1
    for (int s = 1; s <= N_SC; ++s) {
        // conv1 for scale u = s-1 into ring slot s&3, cols 1..514
        {
            int u = s - 1;
            float* dstr = shr + (s & 3) * SW;
            const float* wv = w1e + u * 9;
            #pragma unroll
            for (int j = 0; j < 3; ++j) {
                int c = 1 + tid + (j << 8);         // 1+tid, 257+tid, 513+tid
                if (j < 2 || tid < 2) {
                    const float* p1 = scw + u * SW + (c - 1);
                    float v = b1v;
                    if (u > 0)  v = conv_row(p1 - SW, wv,     v);
                    v = conv_row(p1, wv + 3, v);
                    if (u < 15) v = conv_row(p1 + SW, wv + 6, v);
                    int t = t0 - 2 + c;
                    dstr[c] = ((unsigned)t < T_LEN) ? gelu_exact(v) : 0.f;
                }
            }
        }
        __syncthreads();
        if (s >= 2) {
            // conv2 + blend + ratio for scale sc = s-1 (1-based; ring rows sc-1..sc+1)
            int sc = s - 1;
            #pragma unroll
            for (int j = 0; j < 2; ++j) {
                int c = (j == 0) ? cD0 : cD1;
                float v = b2v;
                if (sc > 1)  v = conv_row(shr + ((sc - 1) & 3) * SW + (c - 1), wl,     v);
                v = conv_row(shr + (sc & 3) * SW + (c - 1), wl + 3, v);
                v = conv_row(shr + ((sc + 1) & 3) * SW + (c - 1), wl + 6, v);
                float h  = gelu_exact(v);
                float cw = scw[(sc - 1) * SW + c];
                float bl = blend * h + (1.f - blend) * cw;
                float r  = __fdividef(bl, cw + 1e-8f);
                if (j == 0) acc0 += r; else acc1 += r;
            }
        }
    }
    // conv2 for scale 16 (ring rows 15, 16; below-row is zero-pad -> skipped)
    {
        int sc = N_SC;
        #pragma unroll
        for (int j = 0; j < 2; ++j) {
            int c = (j == 0) ? cD0 : cD1;
            float v = b2v;
            v = conv_row(shr + ((sc - 1) & 3) * SW + (c - 1), wl,     v);
            v = conv_row(shr + (sc & 3) * SW + (c - 1), wl + 3, v);
            float h  = gelu_exact(v);
            float cw = scw[(sc - 1) * SW + c];
            float bl = blend * h + (1.f - blend) * cw;
            float r  = __fdividef(bl, cw + 1e-8f);
            if (j == 0) acc0 += r; else acc1 += r;
        }
    }
    out[(size_t)row * T_LEN + (t0 + cD0 - 2)] = sx[cD0 + 256] * acc0 * (1.f / 16.f);
    out[(size_t)row * T_LEN + (t0 + cD1 - 2)] = sx[cD1 + 256] * acc1 * (1.f / 16.f);
}

extern "C" void kernel_launch(void* const* d_in, const int* in_sizes, int n_in,
                              void* d_out, int out_size)
{
    const float* x  = (const float*)d_in[0];
    const float* w1 = (const float*)d_in[1];
    const float* b1 = (const float*)d_in[2];
    const float* w2 = (const float*)d_in[3];
    const float* b2 = (const float*)d_in[4];
    const float* bl = (const float*)d_in[5];
    const float* ls = (const float*)d_in[6];
    float* out = (float*)d_out;

    const int rows = in_sizes[0] / T_LEN;   // B*C = 256

    const size_t smem = (size_t)(SXN + 2 * MAXW + 16 * SW + 4 * SW + 144 + 12) * sizeof(float)
                        + 4 * 16 * sizeof(int);      // = 73,584 B (+1KB resv) -> 3 CTAs/SM
    cudaFuncSetAttribute(wav_main_kernel, cudaFuncAttributeMaxDynamicSharedMemorySize, (int)smem);

    dim3 igrid(5, N_SC);                   // 5 tap-chunks x 16 scales
    wav_init_kernel<<<igrid, 128>>>();
    dim3 grid(T_LEN / TTILE, rows);
    wav_main_kernel<<<grid, NTH, smem>>>(x, w1, b1, w2, b2, bl, ls, out);
}